// round 9
// baseline (speedup 1.0000x reference)
#include <cuda_runtime.h>
#include <cuda_fp16.h>
#include <math.h>
#include <stdint.h>

// Problem constants: N=20000, E=640000, S=128, V=16, E_DIM=32
#define MAXN 20000

__device__ float g_agg_s[MAXN * 128];
__device__ float g_agg_v[MAXN * 48];

// Pre-converted fp16 hi/lo weights (row-major [k][n]); W1 padded to 336 rows.
__device__ __half g_W1hi[336 * 128];
__device__ __half g_W1lo[336 * 128];
__device__ __half g_W2hi[128 * 128];
__device__ __half g_W2lo[128 * 128];

__device__ __forceinline__ float sigmoidf_(float x) {
    return 1.0f / (1.0f + __expf(-x));
}
__device__ __forceinline__ uint32_t smem_to_u32(const void* p) {
    uint32_t a;
    asm("{ .reg .u64 t; cvta.to.shared.u64 t, %1; cvt.u32.u64 %0, t; }"
        : "=r"(a) : "l"(p));
    return a;
}
__device__ __forceinline__ void ldsm4(uint32_t addr, uint32_t* r) {
    asm volatile("ldmatrix.sync.aligned.m8n8.x4.shared.b16 {%0,%1,%2,%3}, [%4];"
        : "=r"(r[0]), "=r"(r[1]), "=r"(r[2]), "=r"(r[3]) : "r"(addr));
}
__device__ __forceinline__ void ldsm4t(uint32_t addr, uint32_t* r) {
    asm volatile("ldmatrix.sync.aligned.m8n8.x4.trans.shared.b16 {%0,%1,%2,%3}, [%4];"
        : "=r"(r[0]), "=r"(r[1]), "=r"(r[2]), "=r"(r[3]) : "r"(addr));
}
__device__ __forceinline__ void mma_f16(float* c, const uint32_t* a, const uint32_t* b) {
    asm volatile(
        "mma.sync.aligned.m16n8k16.row.col.f32.f16.f16.f32 "
        "{%0,%1,%2,%3}, {%4,%5,%6,%7}, {%8,%9}, {%0,%1,%2,%3};"
        : "+f"(c[0]), "+f"(c[1]), "+f"(c[2]), "+f"(c[3])
        : "r"(a[0]), "r"(a[1]), "r"(a[2]), "r"(a[3]), "r"(b[0]), "r"(b[1]));
}
__device__ __forceinline__ uint32_t pack_h2(float x0, float x1) {
    __half2 t = __floats2half2_rn(x0, x1);
    return *(uint32_t*)&t;
}
__device__ __forceinline__ void red4(float* p, float a, float b, float c, float d) {
    asm volatile("red.global.add.v4.f32 [%0], {%1, %2, %3, %4};"
        :: "l"(p), "f"(a), "f"(b), "f"(c), "f"(d) : "memory");
}

// ---------------------------------------------------------------------------
__global__ void zero_kernel(int n) {
    int total = n * 176;
    for (int i = blockIdx.x * blockDim.x + threadIdx.x; i < total;
         i += gridDim.x * blockDim.x) {
        if (i < n * 128) g_agg_s[i] = 0.0f;
        else             g_agg_v[i - n * 128] = 0.0f;
    }
}

// One-time weight conversion to fp16 hi/lo.
__global__ void prep_weights(const float* __restrict__ W1,
                             const float* __restrict__ W2) {
    int i = blockIdx.x * blockDim.x + threadIdx.x;
    if (i < 336 * 128) {
        int k = i >> 7;
        float val = (k < 322) ? W1[i] : 0.0f;
        __half h = __float2half_rn(val);
        g_W1hi[i] = h;
        g_W1lo[i] = __float2half_rn(val - __half2float(h));
    } else if (i < 336 * 128 + 128 * 128) {
        int j = i - 336 * 128;
        float val = W2[j];
        __half h = __float2half_rn(val);
        g_W2hi[j] = h;
        g_W2lo[j] = __float2half_rn(val - __half2float(h));
    }
}

// ===========================================================================
// Edge kernel: 128 edges/CTA, 256 threads, mma.sync fp16 (W hi/lo 2-term),
// pre-converted weights + double-buffered software-pipelined tiles.
// smem byte map (total 106624):
//   [0,34816)    T hi [128][136]fp16 @0 (GEMM2 A operand)
//   [34816,..)   during GEMM1: X tile dbl-buf @34816+b*6144 (hi only, [128]x48B)
//   after GEMM2: sms f32[128][132] @0 ; then svin f32[128][100] @0
//   [69632,88064) snorm f32[128][36]   (GEMM1 only)
//                after: WgT f32[16][128] @69632 ; Wv @77824 ; sg @79936
//   [88192,105600) W tile dbl-buf: buf b @88192+b*8704 (hi 16x272B, lo @+4352)
//   [105600,106624) ssrc int[128] @105600 ; sdst @106112
// ===========================================================================
#define OB_T     0
#define OB_X     34816
#define OB_NORM  69632
#define OB_WGT   69632
#define OB_WV    77824
#define OB_SG    79936
#define OB_W     88192
#define OB_SRC   105600
#define OB_DST   106112
#define EDGE_SMEM_BYTES 106624
#define XBUF(b)  (OB_X + (b) * 6144)
#define WBUF(b)  (OB_W + (b) * 8704)
#define WLO_OFF  4352

__device__ __forceinline__ float fetch_x(int k, int e, int eg,
    const float* __restrict__ s, const float* __restrict__ es,
    const int* ssrc, const int* sdst, const float* snorm)
{
    if (k < 128)  return s[ssrc[e] * 128 + k];
    if (k < 256)  return s[sdst[e] * 128 + (k - 128)];
    if (k < 288)  return es[eg * 32 + (k - 256)];
    if (k == 288) return snorm[e * 36 + 32];      // edge_len = |edge_v|
    if (k < 322)  return snorm[e * 36 + (k - 289)];
    return 0.0f;                                  // K padding 322..335
}

__global__ __launch_bounds__(256, 2) void edge_kernel(
    const float* __restrict__ s, const float* __restrict__ v,
    const int* __restrict__ ei, const float* __restrict__ es,
    const float* __restrict__ ev,
    const float* __restrict__ b1, const float* __restrict__ b2,
    const float* __restrict__ Wv, const float* __restrict__ Wg,
    const float* __restrict__ bg, int E)
{
    extern __shared__ __align__(16) char smraw[];
    float* smf = (float*)smraw;
    const uint32_t smb = smem_to_u32(smraw);

    const int tid = threadIdx.x;
    const int lane = tid & 31;
    const int wid = tid >> 5;
    const int e0 = blockIdx.x * 128;
    const int nval = min(128, E - e0);

    int* ssrc = (int*)(smraw + OB_SRC);
    int* sdst = (int*)(smraw + OB_DST);
    float* snorm = (float*)(smraw + OB_NORM);

    // ---- phase 1: indices + vector norms ----
    if (tid < 128) {
        int ee = e0 + min(tid, nval - 1);
        ssrc[tid] = ei[ee];
        sdst[tid] = ei[E + ee];
    }
    __syncthreads();
    for (int q = tid; q < 128 * 33; q += 256) {
        int e = q / 33, j = q - e * 33;
        int eg = e0 + min(e, nval - 1);
        float a, b, c;
        if (j < 16) {
            const float* p = v + (size_t)ssrc[e] * 48 + j * 3;
            a = p[0]; b = p[1]; c = p[2];
        } else if (j < 32) {
            const float* p = v + (size_t)sdst[e] * 48 + (j - 16) * 3;
            a = p[0]; b = p[1]; c = p[2];
        } else {
            const float* p = ev + (size_t)eg * 3;
            a = p[0]; b = p[1]; c = p[2];
        }
        snorm[e * 36 + j] = sqrtf(fmaxf(a * a + b * b + c * c, 1e-8f));
    }
    __syncthreads();

    // warp tiling: 4 warps along M (edges), 2 along N
    const int mw = (wid & 3) * 32;
    const int nw = (wid >> 2) * 64;
    const int arow = lane & 15;
    const int acol = lane >> 4;

    // per-thread tile-build coordinates
    const int xe_base = tid >> 3;          // e for item0 (items step e by 32)
    const int xk2 = (tid & 7) * 2;         // k pair within tile
    const int wkk = tid >> 4;              // W tile row
    const int wn8 = (tid & 15) * 8;        // W tile col group

    float acc[2][8][4];
#pragma unroll
    for (int mt = 0; mt < 2; ++mt)
#pragma unroll
        for (int nt = 0; nt < 8; ++nt)
#pragma unroll
            for (int r = 0; r < 4; ++r) acc[mt][nt][r] = 0.0f;

    float xr[4][2];
    uint4 wh, wl;

    // ---- prologue: tile 0 ----
    {
#pragma unroll
        for (int it = 0; it < 4; ++it) {
            int e = xe_base + it * 32;
            int eg = e0 + min(e, nval - 1);
            xr[it][0] = fetch_x(xk2,     e, eg, s, es, ssrc, sdst, snorm);
            xr[it][1] = fetch_x(xk2 + 1, e, eg, s, es, ssrc, sdst, snorm);
        }
        wh = *(const uint4*)&g_W1hi[wkk * 128 + wn8];
        wl = *(const uint4*)&g_W1lo[wkk * 128 + wn8];
#pragma unroll
        for (int it = 0; it < 4; ++it) {
            int e = xe_base + it * 32;
            *(uint32_t*)(smraw + XBUF(0) + e * 48 + xk2 * 2) =
                pack_h2(xr[it][0], xr[it][1]);
        }
        *(uint4*)(smraw + WBUF(0) + wkk * 272 + wn8 * 2) = wh;
        *(uint4*)(smraw + WBUF(0) + WLO_OFF + wkk * 272 + wn8 * 2) = wl;
    }
    __syncthreads();

    // ================= GEMM1: h = X @ W1  (K=336, 21 tiles) ==================
    for (int kt = 0; kt < 21; ++kt) {
        const int cur = kt & 1, nxt = cur ^ 1;
        const bool more = (kt + 1 < 21);
        if (more) {
            int kbase = (kt + 1) * 16;
#pragma unroll
            for (int it = 0; it < 4; ++it) {
                int e = xe_base + it * 32;
                int eg = e0 + min(e, nval - 1);
                xr[it][0] = fetch_x(kbase + xk2,     e, eg, s, es, ssrc, sdst, snorm);
                xr[it][1] = fetch_x(kbase + xk2 + 1, e, eg, s, es, ssrc, sdst, snorm);
            }
            wh = *(const uint4*)&g_W1hi[(kbase + wkk) * 128 + wn8];
            wl = *(const uint4*)&g_W1lo[(kbase + wkk) * 128 + wn8];
        }

        // mma on current buffer (2-term: A*Whi + A*Wlo)
        {
            uint32_t ah[2][4];
#pragma unroll
            for (int mt = 0; mt < 2; ++mt) {
                uint32_t aaddr = smb + XBUF(cur) + (mw + 16 * mt + arow) * 48 + acol * 16;
                ldsm4(aaddr, ah[mt]);
            }
#pragma unroll
            for (int nb = 0; nb < 4; ++nb) {
                uint32_t bh[4], bl[4];
                uint32_t baddr = smb + WBUF(cur) + arow * 272 + (nw + nb * 16 + acol * 8) * 2;
                ldsm4t(baddr, bh);
                ldsm4t(baddr + WLO_OFF, bl);
#pragma unroll
                for (int mt = 0; mt < 2; ++mt) {
                    mma_f16(acc[mt][2 * nb],     ah[mt], bh);
                    mma_f16(acc[mt][2 * nb + 1], ah[mt], bh + 2);
                    mma_f16(acc[mt][2 * nb],     ah[mt], bl);
                    mma_f16(acc[mt][2 * nb + 1], ah[mt], bl + 2);
                }
            }
        }

        if (more) {
#pragma unroll
            for (int it = 0; it < 4; ++it) {
                int e = xe_base + it * 32;
                *(uint32_t*)(smraw + XBUF(nxt) + e * 48 + xk2 * 2) =
                    pack_h2(xr[it][0], xr[it][1]);
            }
            *(uint4*)(smraw + WBUF(nxt) + wkk * 272 + wn8 * 2) = wh;
            *(uint4*)(smraw + WBUF(nxt) + WLO_OFF + wkk * 272 + wn8 * 2) = wl;
        }
        __syncthreads();
    }

    // ---- epilogue 1: +b1, silu -> T fp16 (X bufs dead) ----
#pragma unroll
    for (int mt = 0; mt < 2; ++mt) {
        int r0 = mw + 16 * mt + (lane >> 2);
#pragma unroll
        for (int nt = 0; nt < 8; ++nt) {
            int n = nw + nt * 8 + (lane & 3) * 2;
            float2 bb = *(const float2*)&b1[n];
            float h0 = acc[mt][nt][0] + bb.x, h1 = acc[mt][nt][1] + bb.y;
            float h2 = acc[mt][nt][2] + bb.x, h3 = acc[mt][nt][3] + bb.y;
            float t0 = h0 * sigmoidf_(h0), t1 = h1 * sigmoidf_(h1);
            float t2 = h2 * sigmoidf_(h2), t3 = h3 * sigmoidf_(h3);
            *(uint32_t*)(smraw + OB_T + r0 * 272 + n * 2)       = pack_h2(t0, t1);
            *(uint32_t*)(smraw + OB_T + (r0 + 8) * 272 + n * 2) = pack_h2(t2, t3);
        }
    }
    __syncthreads();

    // stage Wg^T and Wv (norm region dead)
    for (int q = tid; q < 2048; q += 256) {
        int w = q >> 7, c = q & 127;
        smf[OB_WGT / 4 + q] = Wg[c * 16 + w];
    }
    for (int q = tid; q < 528; q += 256) smf[OB_WV / 4 + q] = Wv[q];

    // ================= GEMM2: m_s = silu(h) @ W2  (K=128, 8 tiles) ===========
#pragma unroll
    for (int mt = 0; mt < 2; ++mt)
#pragma unroll
        for (int nt = 0; nt < 8; ++nt)
#pragma unroll
            for (int r = 0; r < 4; ++r) acc[mt][nt][r] = 0.0f;

    wh = *(const uint4*)&g_W2hi[wkk * 128 + wn8];
    wl = *(const uint4*)&g_W2lo[wkk * 128 + wn8];
    *(uint4*)(smraw + WBUF(0) + wkk * 272 + wn8 * 2) = wh;
    *(uint4*)(smraw + WBUF(0) + WLO_OFF + wkk * 272 + wn8 * 2) = wl;
    __syncthreads();

    for (int kt = 0; kt < 8; ++kt) {
        const int cur = kt & 1, nxt = cur ^ 1;
        const bool more = (kt + 1 < 8);
        if (more) {
            wh = *(const uint4*)&g_W2hi[((kt + 1) * 16 + wkk) * 128 + wn8];
            wl = *(const uint4*)&g_W2lo[((kt + 1) * 16 + wkk) * 128 + wn8];
        }
        {
            uint32_t ah[2][4];
#pragma unroll
            for (int mt = 0; mt < 2; ++mt) {
                uint32_t aaddr = smb + OB_T + (mw + 16 * mt + arow) * 272
                               + (kt * 16 + acol * 8) * 2;
                ldsm4(aaddr, ah[mt]);
            }
#pragma unroll
            for (int nb = 0; nb < 4; ++nb) {
                uint32_t bh[4], bl[4];
                uint32_t baddr = smb + WBUF(cur) + arow * 272 + (nw + nb * 16 + acol * 8) * 2;
                ldsm4t(baddr, bh);
                ldsm4t(baddr + WLO_OFF, bl);
#pragma unroll
                for (int mt = 0; mt < 2; ++mt) {
                    mma_f16(acc[mt][2 * nb],     ah[mt], bh);
                    mma_f16(acc[mt][2 * nb + 1], ah[mt], bh + 2);
                    mma_f16(acc[mt][2 * nb],     ah[mt], bl);
                    mma_f16(acc[mt][2 * nb + 1], ah[mt], bl + 2);
                }
            }
        }
        if (more) {
            *(uint4*)(smraw + WBUF(nxt) + wkk * 272 + wn8 * 2) = wh;
            *(uint4*)(smraw + WBUF(nxt) + WLO_OFF + wkk * 272 + wn8 * 2) = wl;
        }
        __syncthreads();
    }

    // ---- epilogue 2: +b2 -> sms (aliases T; all T reads complete) ----
    float* sms = smf;  // [128][132]
#pragma unroll
    for (int mt = 0; mt < 2; ++mt) {
        int r0 = mw + 16 * mt + (lane >> 2);
#pragma unroll
        for (int nt = 0; nt < 8; ++nt) {
            int n = nw + nt * 8 + (lane & 3) * 2;
            float2 bb = *(const float2*)&b2[n];
            sms[r0 * 132 + n]       = acc[mt][nt][0] + bb.x;
            sms[r0 * 132 + n + 1]   = acc[mt][nt][1] + bb.y;
            sms[(r0 + 8) * 132 + n]     = acc[mt][nt][2] + bb.x;
            sms[(r0 + 8) * 132 + n + 1] = acc[mt][nt][3] + bb.y;
        }
    }
    __syncthreads();

    // ---- gates: sigmoid(ms @ Wg + bg) ----
    float* sg = smf + OB_SG / 4;
    for (int q = tid; q < 2048; q += 256) {
        int e = q >> 4, w = q & 15;
        float g = 0.0f;
        const float4* ms4 = (const float4*)(sms + e * 132);
        const float4* wg4 = (const float4*)(smf + OB_WGT / 4 + w * 128);
#pragma unroll 8
        for (int c4 = 0; c4 < 32; ++c4) {
            float4 a = ms4[c4], b = wg4[c4];
            g += a.x * b.x + a.y * b.y + a.z * b.z + a.w * b.w;
        }
        sg[e * 16 + w] = sigmoidf_(g + bg[w]);
    }
    __syncthreads();

    // ---- scatter-add m_s ----
    for (int q = tid; q < 4096; q += 256) {
        int e = q >> 5, cq = q & 31;
        if (e < nval) {
            const float* p = sms + e * 132 + cq * 4;
            red4(&g_agg_s[(size_t)sdst[e] * 128 + cq * 4], p[0], p[1], p[2], p[3]);
        }
    }
    __syncthreads();

    // ---- gather vin (aliases sms, dead) ----
    float* svin = smf;  // [128][100]
    for (int q = tid; q < 128 * 99; q += 256) {
        int e = q / 99, j = q - e * 99;
        int eg = e0 + min(e, nval - 1);
        float val;
        if (j < 48)      val = v[(size_t)ssrc[e] * 48 + j];
        else if (j < 96) val = v[(size_t)sdst[e] * 48 + (j - 48)];
        else             val = ev[(size_t)eg * 3 + (j - 96)];
        svin[e * 100 + j] = val;
    }
    __syncthreads();

    // ---- v projection * gate, scatter-add ----
    for (int q = tid; q < 1536; q += 256) {
        int e = q / 12, rq = q - e * 12;
        if (e >= nval) continue;
        float out[4];
#pragma unroll
        for (int u = 0; u < 4; ++u) {
            int r = rq * 4 + u, w = r / 3, c3 = r - w * 3;
            float a = 0.0f;
#pragma unroll
            for (int j = 0; j < 33; ++j)
                a = fmaf(svin[e * 100 + j * 3 + c3], smf[OB_WV / 4 + j * 16 + w], a);
            out[u] = a * sg[e * 16 + w];
        }
        red4(&g_agg_v[(size_t)sdst[e] * 48 + rq * 4], out[0], out[1], out[2], out[3]);
    }
}

// ---------------------------------------------------------------------------
// Node update kernel (r1, verified correct)
// ---------------------------------------------------------------------------
__global__ __launch_bounds__(128) void node_kernel(
    const float* __restrict__ s, const float* __restrict__ v,
    const float* __restrict__ W1, const float* __restrict__ b1,
    const float* __restrict__ W2, const float* __restrict__ b2,
    const float* __restrict__ Wv, const float* __restrict__ Wg,
    const float* __restrict__ bg, const float* __restrict__ lng,
    const float* __restrict__ lnb,
    float* __restrict__ out_s, float* __restrict__ out_v, int n)
{
    __shared__ float xu[8][292];
    __shared__ float vin[8][96];
    __shared__ float tt[8][128];
    __shared__ float dsm[8][132];
    __shared__ float gate[8][16];
    __shared__ float rsum[8][4], rsq[8][4];

    const int tid = threadIdx.x;
    const int n0 = blockIdx.x * 8;

    for (int idx = tid; idx < 8 * 256; idx += 128) {
        int i = idx >> 8, k = idx & 255;
        int nd = min(n0 + i, n - 1);
        xu[i][k] = (k < 128) ? s[nd * 128 + k] : g_agg_s[nd * 128 + (k - 128)];
    }
    for (int idx = tid; idx < 8 * 96; idx += 128) {
        int i = idx / 96, k = idx - i * 96;
        int nd = min(n0 + i, n - 1);
        vin[i][k] = (k < 48) ? v[nd * 48 + k] : g_agg_v[nd * 48 + (k - 48)];
    }
    __syncthreads();
    for (int idx = tid; idx < 8 * 32; idx += 128) {
        int i = idx >> 5, j = idx & 31;
        float a = vin[i][j * 3], b = vin[i][j * 3 + 1], c = vin[i][j * 3 + 2];
        xu[i][256 + j] = sqrtf(fmaxf(a * a + b * b + c * c, 1e-8f));
    }
    __syncthreads();

    const int c = tid;
    float acc[8];
    {
        float bb = b1[c];
#pragma unroll
        for (int i = 0; i < 8; ++i) acc[i] = bb;
    }
    for (int k = 0; k < 288; ++k) {
        float w = W1[k * 128 + c];
#pragma unroll
        for (int i = 0; i < 8; ++i) acc[i] = fmaf(xu[i][k], w, acc[i]);
    }
#pragma unroll
    for (int i = 0; i < 8; ++i) {
        float h = acc[i];
        tt[i][c] = h * sigmoidf_(h);
    }
    __syncthreads();

    float acc2[8];
    {
        float bb = b2[c];
#pragma unroll
        for (int i = 0; i < 8; ++i) acc2[i] = bb;
    }
    for (int k = 0; k < 128; ++k) {
        float w = W2[k * 128 + c];
#pragma unroll
        for (int i = 0; i < 8; ++i) acc2[i] = fmaf(tt[i][k], w, acc2[i]);
    }
#pragma unroll
    for (int i = 0; i < 8; ++i) dsm[i][c] = acc2[i];
    __syncthreads();

    {
        int i = tid >> 4, w = tid & 15;
        float g = bg[w];
        for (int cc = 0; cc < 128; ++cc)
            g = fmaf(dsm[i][cc], Wg[cc * 16 + w], g);
        gate[i][w] = sigmoidf_(g);
    }

    float val[8];
#pragma unroll
    for (int i = 0; i < 8; ++i) {
        int nd = min(n0 + i, n - 1);
        val[i] = s[nd * 128 + c] + acc2[i];
    }
    const int lane = tid & 31, wq = tid >> 5;
    float psum[8], psq[8];
#pragma unroll
    for (int i = 0; i < 8; ++i) { psum[i] = val[i]; psq[i] = val[i] * val[i]; }
#pragma unroll
    for (int off = 16; off > 0; off >>= 1) {
#pragma unroll
        for (int i = 0; i < 8; ++i) {
            psum[i] += __shfl_xor_sync(0xffffffffu, psum[i], off);
            psq[i]  += __shfl_xor_sync(0xffffffffu, psq[i],  off);
        }
    }
    if (lane == 0) {
#pragma unroll
        for (int i = 0; i < 8; ++i) { rsum[i][wq] = psum[i]; rsq[i][wq] = psq[i]; }
    }
    __syncthreads();

#pragma unroll
    for (int i = 0; i < 8; ++i) {
        if (n0 + i >= n) continue;
        float sum = rsum[i][0] + rsum[i][1] + rsum[i][2] + rsum[i][3];
        float sq  = rsq[i][0] + rsq[i][1] + rsq[i][2] + rsq[i][3];
        float mu  = sum * (1.0f / 128.0f);
        float var = sq * (1.0f / 128.0f) - mu * mu;
        float o = (val[i] - mu) * rsqrtf(var + 1e-5f) * lng[c] + lnb[c];
        out_s[(n0 + i) * 128 + c] = o;
    }

    for (int q = tid; q < 8 * 48; q += 128) {
        int i = q / 48, r = q - i * 48;
        if (n0 + i >= n) continue;
        int w = r / 3, cc = r - w * 3;
        float a = 0.0f;
#pragma unroll
        for (int j = 0; j < 32; ++j)
            a = fmaf(vin[i][j * 3 + cc], Wv[j * 16 + w], a);
        a *= gate[i][w];
        out_v[(n0 + i) * 48 + r] = v[(n0 + i) * 48 + r] + a;
    }
}

// ---------------------------------------------------------------------------
extern "C" void kernel_launch(void* const* d_in, const int* in_sizes, int n_in,
                              void* d_out, int out_size)
{
    const float* s   = (const float*)d_in[0];
    const float* v   = (const float*)d_in[1];
    const int*   ei  = (const int*)  d_in[2];
    const float* es  = (const float*)d_in[3];
    const float* ev  = (const float*)d_in[4];
    const float* mW1 = (const float*)d_in[5];
    const float* mb1 = (const float*)d_in[6];
    const float* mW2 = (const float*)d_in[7];
    const float* mb2 = (const float*)d_in[8];
    const float* mWv = (const float*)d_in[9];
    const float* mWg = (const float*)d_in[10];
    const float* mbg = (const float*)d_in[11];
    const float* uW1 = (const float*)d_in[12];
    const float* ub1 = (const float*)d_in[13];
    const float* uW2 = (const float*)d_in[14];
    const float* ub2 = (const float*)d_in[15];
    const float* uWv = (const float*)d_in[16];
    const float* uWg = (const float*)d_in[17];
    const float* ubg = (const float*)d_in[18];
    const float* lng = (const float*)d_in[19];
    const float* lnb = (const float*)d_in[20];

    const int n = in_sizes[0] / 128;
    const int E = in_sizes[2] / 2;

    float* out_s = (float*)d_out;
    float* out_v = out_s + (size_t)n * 128;

    cudaFuncSetAttribute(edge_kernel,
                         cudaFuncAttributeMaxDynamicSharedMemorySize,
                         EDGE_SMEM_BYTES);

    zero_kernel<<<(n * 176 + 255) / 256, 256>>>(n);
    prep_weights<<<(336 * 128 + 128 * 128 + 255) / 256, 256>>>(mW1, mW2);

    edge_kernel<<<(E + 127) / 128, 256, EDGE_SMEM_BYTES>>>(
        s, v, ei, es, ev, mb1, mb2, mWv, mWg, mbg, E);

    node_kernel<<<(n + 7) / 8, 128>>>(
        s, v, uW1, ub1, uW2, ub2, uWv, uWg, ubg, lng, lnb,
        out_s, out_v, n);
}

// round 10
// speedup vs baseline: 2.0937x; 2.0937x over previous
#include <cuda_runtime.h>
#include <cuda_fp16.h>
#include <math.h>
#include <stdint.h>

// Problem constants: N=20000, E=640000, S=128, V=16, E_DIM=32
#define MAXN 20000

__device__ float g_agg_s[MAXN * 128];
__device__ float g_agg_v[MAXN * 48];

// Per-node precomputed partial products: Y1 = s @ W1[0:128], Y2 = s @ W1[128:256]
__device__ float g_Y1[MAXN * 128];
__device__ float g_Y2[MAXN * 128];

// Pre-converted fp16 hi/lo weights (row-major [k][n]).
__device__ __half g_W1ahi[128 * 128];  // W1 rows 0..127
__device__ __half g_W1alo[128 * 128];
__device__ __half g_W1bhi[128 * 128];  // W1 rows 128..255
__device__ __half g_W1blo[128 * 128];
__device__ __half g_W1phi[80 * 128];   // W1 rows 256..321 (edge-local), padded to 80
__device__ __half g_W1plo[80 * 128];
__device__ __half g_W2hi[128 * 128];
__device__ __half g_W2lo[128 * 128];
__device__ __half g_Wgphi[128 * 16];   // W2 @ Wg (fused gate)
__device__ __half g_Wgplo[128 * 16];
__device__ float  g_bgp[16];           // b2 @ Wg + bg

__device__ __forceinline__ float sigmoidf_(float x) {
    return 1.0f / (1.0f + __expf(-x));
}
__device__ __forceinline__ uint32_t smem_to_u32(const void* p) {
    uint32_t a;
    asm("{ .reg .u64 t; cvta.to.shared.u64 t, %1; cvt.u32.u64 %0, t; }"
        : "=r"(a) : "l"(p));
    return a;
}
__device__ __forceinline__ void ldsm4(uint32_t addr, uint32_t* r) {
    asm volatile("ldmatrix.sync.aligned.m8n8.x4.shared.b16 {%0,%1,%2,%3}, [%4];"
        : "=r"(r[0]), "=r"(r[1]), "=r"(r[2]), "=r"(r[3]) : "r"(addr));
}
__device__ __forceinline__ void ldsm4t(uint32_t addr, uint32_t* r) {
    asm volatile("ldmatrix.sync.aligned.m8n8.x4.trans.shared.b16 {%0,%1,%2,%3}, [%4];"
        : "=r"(r[0]), "=r"(r[1]), "=r"(r[2]), "=r"(r[3]) : "r"(addr));
}
__device__ __forceinline__ void mma_f16(float* c, const uint32_t* a, const uint32_t* b) {
    asm volatile(
        "mma.sync.aligned.m16n8k16.row.col.f32.f16.f16.f32 "
        "{%0,%1,%2,%3}, {%4,%5,%6,%7}, {%8,%9}, {%0,%1,%2,%3};"
        : "+f"(c[0]), "+f"(c[1]), "+f"(c[2]), "+f"(c[3])
        : "r"(a[0]), "r"(a[1]), "r"(a[2]), "r"(a[3]), "r"(b[0]), "r"(b[1]));
}
__device__ __forceinline__ uint32_t pack_h2(float x0, float x1) {
    __half2 t = __floats2half2_rn(x0, x1);
    return *(uint32_t*)&t;
}
__device__ __forceinline__ void red4(float* p, float a, float b, float c, float d) {
    asm volatile("red.global.add.v4.f32 [%0], {%1, %2, %3, %4};"
        :: "l"(p), "f"(a), "f"(b), "f"(c), "f"(d) : "memory");
}

// ---------------------------------------------------------------------------
__global__ void zero_kernel(int n) {
    int total = n * 176;
    for (int i = blockIdx.x * blockDim.x + threadIdx.x; i < total;
         i += gridDim.x * blockDim.x) {
        if (i < n * 128) g_agg_s[i] = 0.0f;
        else             g_agg_v[i - n * 128] = 0.0f;
    }
}

// One-time weight conversion / fusion.
// ranges: [0,10240) W1p | [10240,26624) W1a | [26624,43008) W1b |
//         [43008,59392) W2 | [59392,61440) Wgp | [61440,61456) bgp
__global__ void prep_weights(const float* __restrict__ W1,
                             const float* __restrict__ W2,
                             const float* __restrict__ b2,
                             const float* __restrict__ Wg,
                             const float* __restrict__ bg) {
    int i = blockIdx.x * blockDim.x + threadIdx.x;
    if (i < 80 * 128) {
        int k = i >> 7;
        float val = (k < 66) ? W1[(256 + k) * 128 + (i & 127)] : 0.0f;
        __half h = __float2half_rn(val);
        g_W1phi[i] = h;
        g_W1plo[i] = __float2half_rn(val - __half2float(h));
    } else if (i < 26624) {
        int j = i - 10240;
        float val = W1[j];
        __half h = __float2half_rn(val);
        g_W1ahi[j] = h;
        g_W1alo[j] = __float2half_rn(val - __half2float(h));
    } else if (i < 43008) {
        int j = i - 26624;
        float val = W1[128 * 128 + j];
        __half h = __float2half_rn(val);
        g_W1bhi[j] = h;
        g_W1blo[j] = __float2half_rn(val - __half2float(h));
    } else if (i < 59392) {
        int j = i - 43008;
        float val = W2[j];
        __half h = __float2half_rn(val);
        g_W2hi[j] = h;
        g_W2lo[j] = __float2half_rn(val - __half2float(h));
    } else if (i < 61440) {
        int j = i - 59392;
        int k = j >> 4, w = j & 15;
        float a = 0.0f;
        for (int c = 0; c < 128; ++c)
            a = fmaf(W2[k * 128 + c], Wg[c * 16 + w], a);
        __half h = __float2half_rn(a);
        g_Wgphi[j] = h;
        g_Wgplo[j] = __float2half_rn(a - __half2float(h));
    } else if (i < 61456) {
        int w = i - 61440;
        float a = bg[w];
        for (int c = 0; c < 128; ++c)
            a = fmaf(b2[c], Wg[c * 16 + w], a);
        g_bgp[w] = a;
    }
}

// ---------------------------------------------------------------------------
// Y kernel: per-node partials Y1 = s @ W1a, Y2 = s @ W1b (fp16 2-term, mma).
// 128 nodes/CTA, 256 threads, same warp tiling as edge kernel.
// ---------------------------------------------------------------------------
__global__ __launch_bounds__(256) void y_kernel(const float* __restrict__ s, int n) {
    __shared__ __align__(16) char ysm[6144 + 8704];
    const uint32_t smb = smem_to_u32(ysm);
    const int tid = threadIdx.x;
    const int lane = tid & 31;
    const int wid = tid >> 5;
    const int n0 = blockIdx.x * 128;

    const int mw = (wid & 3) * 32;
    const int nw = (wid >> 2) * 64;
    const int arow = lane & 15;
    const int acol = lane >> 4;

    for (int g = 0; g < 2; ++g) {
        const __half* Whi = g ? g_W1bhi : g_W1ahi;
        const __half* Wlo = g ? g_W1blo : g_W1alo;
        float acc[2][8][4];
#pragma unroll
        for (int mt = 0; mt < 2; ++mt)
#pragma unroll
            for (int nt = 0; nt < 8; ++nt)
#pragma unroll
                for (int r = 0; r < 4; ++r) acc[mt][nt][r] = 0.0f;

        for (int kt = 0; kt < 8; ++kt) {
            for (int q = tid; q < 2048; q += 256) {
                int e = q >> 4, kk = q & 15;
                int nd = min(n0 + e, n - 1);
                *(__half*)(ysm + e * 48 + kk * 2) =
                    __float2half_rn(s[nd * 128 + kt * 16 + kk]);
            }
            for (int q = tid; q < 2048; q += 256) {
                int kk = q >> 7, nc = q & 127;
                *(__half*)(ysm + 6144 + kk * 272 + nc * 2) = Whi[(kt * 16 + kk) * 128 + nc];
                *(__half*)(ysm + 6144 + 4352 + kk * 272 + nc * 2) = Wlo[(kt * 16 + kk) * 128 + nc];
            }
            __syncthreads();
            uint32_t ah[2][4];
#pragma unroll
            for (int mt = 0; mt < 2; ++mt)
                ldsm4(smb + (mw + 16 * mt + arow) * 48 + acol * 16, ah[mt]);
#pragma unroll
            for (int nb = 0; nb < 4; ++nb) {
                uint32_t bh[4], bl[4];
                uint32_t baddr = smb + 6144 + arow * 272 + (nw + nb * 16 + acol * 8) * 2;
                ldsm4t(baddr, bh);
                ldsm4t(baddr + 4352, bl);
#pragma unroll
                for (int mt = 0; mt < 2; ++mt) {
                    mma_f16(acc[mt][2 * nb],     ah[mt], bh);
                    mma_f16(acc[mt][2 * nb + 1], ah[mt], bh + 2);
                    mma_f16(acc[mt][2 * nb],     ah[mt], bl);
                    mma_f16(acc[mt][2 * nb + 1], ah[mt], bl + 2);
                }
            }
            __syncthreads();
        }
        float* Y = g ? g_Y2 : g_Y1;
#pragma unroll
        for (int mt = 0; mt < 2; ++mt) {
            int r0 = mw + 16 * mt + (lane >> 2);
#pragma unroll
            for (int nt = 0; nt < 8; ++nt) {
                int nc = nw + nt * 8 + (lane & 3) * 2;
                if (n0 + r0 < n) {
                    float2 u = make_float2(acc[mt][nt][0], acc[mt][nt][1]);
                    *(float2*)&Y[(size_t)(n0 + r0) * 128 + nc] = u;
                }
                if (n0 + r0 + 8 < n) {
                    float2 u = make_float2(acc[mt][nt][2], acc[mt][nt][3]);
                    *(float2*)&Y[(size_t)(n0 + r0 + 8) * 128 + nc] = u;
                }
            }
        }
    }
}

// ===========================================================================
// Edge kernel: 128 edges/CTA, 256 threads.
// GEMM1 K=80 only (node parts hoisted into Y1/Y2, loaded into acc init).
// Gate fused into GEMM2 via Wgp = W2@Wg.
// smem byte map (total 106624):
//   [0,34816)      T [128][136]fp16  (GEMM2 A); later sms f32[128][132]; later svin
//   [34816,47104)  X tile dbl-buf (GEMM1): b*6144, [128]x48B
//   [69632,88064)  snorm f32[128][36] (GEMM1 only)
//                  after: Wgp hi @69632(4KB), lo @73728(4KB); Wv @77824; sg @79936(8KB)
//   [88192,105600) W tile dbl-buf: b @88192+b*8704 (hi 16x272B, lo @+4352)
//   [105600,106624) ssrc @105600 ; sdst @106112
// ===========================================================================
#define OB_T     0
#define OB_X     34816
#define OB_NORM  69632
#define OB_WGP   69632
#define OB_WGPLO 73728
#define OB_WV    77824
#define OB_SG    79936
#define OB_W     88192
#define OB_SRC   105600
#define OB_DST   106112
#define EDGE_SMEM_BYTES 106624
#define XBUF(b)  (OB_X + (b) * 6144)
#define WBUF(b)  (OB_W + (b) * 8704)
#define WLO_OFF  4352

// edge-local X: k 0..31 edge_s, 32 edge_len, 33..65 vn, 66..79 zero
__device__ __forceinline__ float fetch_x80(int k, int e, int eg,
    const float* __restrict__ es, const float* snorm)
{
    if (k < 32)   return es[eg * 32 + k];
    if (k == 32)  return snorm[e * 36 + 32];
    if (k < 66)   return snorm[e * 36 + (k - 33)];
    return 0.0f;
}

__global__ __launch_bounds__(256, 2) void edge_kernel(
    const float* __restrict__ s, const float* __restrict__ v,
    const int* __restrict__ ei, const float* __restrict__ es,
    const float* __restrict__ ev,
    const float* __restrict__ b1, const float* __restrict__ b2,
    const float* __restrict__ Wv, int E)
{
    extern __shared__ __align__(16) char smraw[];
    float* smf = (float*)smraw;
    const uint32_t smb = smem_to_u32(smraw);

    const int tid = threadIdx.x;
    const int lane = tid & 31;
    const int wid = tid >> 5;
    const int e0 = blockIdx.x * 128;
    const int nval = min(128, E - e0);

    int* ssrc = (int*)(smraw + OB_SRC);
    int* sdst = (int*)(smraw + OB_DST);
    float* snorm = (float*)(smraw + OB_NORM);

    // ---- phase 1: indices + vector norms ----
    if (tid < 128) {
        int ee = e0 + min(tid, nval - 1);
        ssrc[tid] = ei[ee];
        sdst[tid] = ei[E + ee];
    }
    __syncthreads();
    for (int q = tid; q < 128 * 33; q += 256) {
        int e = q / 33, j = q - e * 33;
        int eg = e0 + min(e, nval - 1);
        float a, b, c;
        if (j < 16) {
            const float* p = v + (size_t)ssrc[e] * 48 + j * 3;
            a = p[0]; b = p[1]; c = p[2];
        } else if (j < 32) {
            const float* p = v + (size_t)sdst[e] * 48 + (j - 16) * 3;
            a = p[0]; b = p[1]; c = p[2];
        } else {
            const float* p = ev + (size_t)eg * 3;
            a = p[0]; b = p[1]; c = p[2];
        }
        snorm[e * 36 + j] = sqrtf(fmaxf(a * a + b * b + c * c, 1e-8f));
    }
    __syncthreads();

    const int mw = (wid & 3) * 32;
    const int nw = (wid >> 2) * 64;
    const int arow = lane & 15;
    const int acol = lane >> 4;

    const int xe_base = tid >> 3;
    const int xk2 = (tid & 7) * 2;
    const int wkk = tid >> 4;
    const int wn8 = (tid & 15) * 8;

    float acc[2][8][4];

    // ---- acc init: Y1[src] + Y2[dst] fragments ----
    {
        const int rbase = mw + (lane >> 2);
        const int cbase = nw + (lane & 3) * 2;
#pragma unroll
        for (int mt = 0; mt < 2; ++mt) {
#pragma unroll
            for (int rh = 0; rh < 2; ++rh) {
                int r = rbase + 16 * mt + 8 * rh;
                const float* y1 = g_Y1 + (size_t)ssrc[r] * 128;
                const float* y2 = g_Y2 + (size_t)sdst[r] * 128;
#pragma unroll
                for (int nt = 0; nt < 8; ++nt) {
                    int nc = cbase + nt * 8;
                    float2 a = *(const float2*)&y1[nc];
                    float2 b = *(const float2*)&y2[nc];
                    acc[mt][nt][2 * rh]     = a.x + b.x;
                    acc[mt][nt][2 * rh + 1] = a.y + b.y;
                }
            }
        }
    }

    float xr[4][2];
    uint4 wh, wl;

    // ---- prologue: tile 0 ----
    {
#pragma unroll
        for (int it = 0; it < 4; ++it) {
            int e = xe_base + it * 32;
            int eg = e0 + min(e, nval - 1);
            xr[it][0] = fetch_x80(xk2,     e, eg, es, snorm);
            xr[it][1] = fetch_x80(xk2 + 1, e, eg, es, snorm);
        }
        wh = *(const uint4*)&g_W1phi[wkk * 128 + wn8];
        wl = *(const uint4*)&g_W1plo[wkk * 128 + wn8];
#pragma unroll
        for (int it = 0; it < 4; ++it) {
            int e = xe_base + it * 32;
            *(uint32_t*)(smraw + XBUF(0) + e * 48 + xk2 * 2) =
                pack_h2(xr[it][0], xr[it][1]);
        }
        *(uint4*)(smraw + WBUF(0) + wkk * 272 + wn8 * 2) = wh;
        *(uint4*)(smraw + WBUF(0) + WLO_OFF + wkk * 272 + wn8 * 2) = wl;
    }
    __syncthreads();

    // ================= GEMM1: edge-local part, K=80 (5 tiles) ================
    for (int kt = 0; kt < 5; ++kt) {
        const int cur = kt & 1, nxt = cur ^ 1;
        const bool more = (kt + 1 < 5);
        if (more) {
            int kbase = (kt + 1) * 16;
#pragma unroll
            for (int it = 0; it < 4; ++it) {
                int e = xe_base + it * 32;
                int eg = e0 + min(e, nval - 1);
                xr[it][0] = fetch_x80(kbase + xk2,     e, eg, es, snorm);
                xr[it][1] = fetch_x80(kbase + xk2 + 1, e, eg, es, snorm);
            }
            wh = *(const uint4*)&g_W1phi[(kbase + wkk) * 128 + wn8];
            wl = *(const uint4*)&g_W1plo[(kbase + wkk) * 128 + wn8];
        }
        {
            uint32_t ah[2][4];
#pragma unroll
            for (int mt = 0; mt < 2; ++mt)
                ldsm4(smb + XBUF(cur) + (mw + 16 * mt + arow) * 48 + acol * 16, ah[mt]);
#pragma unroll
            for (int nb = 0; nb < 4; ++nb) {
                uint32_t bh[4], bl[4];
                uint32_t baddr = smb + WBUF(cur) + arow * 272 + (nw + nb * 16 + acol * 8) * 2;
                ldsm4t(baddr, bh);
                ldsm4t(baddr + WLO_OFF, bl);
#pragma unroll
                for (int mt = 0; mt < 2; ++mt) {
                    mma_f16(acc[mt][2 * nb],     ah[mt], bh);
                    mma_f16(acc[mt][2 * nb + 1], ah[mt], bh + 2);
                    mma_f16(acc[mt][2 * nb],     ah[mt], bl);
                    mma_f16(acc[mt][2 * nb + 1], ah[mt], bl + 2);
                }
            }
        }
        if (more) {
#pragma unroll
            for (int it = 0; it < 4; ++it) {
                int e = xe_base + it * 32;
                *(uint32_t*)(smraw + XBUF(nxt) + e * 48 + xk2 * 2) =
                    pack_h2(xr[it][0], xr[it][1]);
            }
            *(uint4*)(smraw + WBUF(nxt) + wkk * 272 + wn8 * 2) = wh;
            *(uint4*)(smraw + WBUF(nxt) + WLO_OFF + wkk * 272 + wn8 * 2) = wl;
        }
        __syncthreads();
    }

    // ---- epilogue 1: +b1, silu -> T fp16 ----
#pragma unroll
    for (int mt = 0; mt < 2; ++mt) {
        int r0 = mw + 16 * mt + (lane >> 2);
#pragma unroll
        for (int nt = 0; nt < 8; ++nt) {
            int n = nw + nt * 8 + (lane & 3) * 2;
            float2 bb = *(const float2*)&b1[n];
            float h0 = acc[mt][nt][0] + bb.x, h1 = acc[mt][nt][1] + bb.y;
            float h2 = acc[mt][nt][2] + bb.x, h3 = acc[mt][nt][3] + bb.y;
            float t0 = h0 * sigmoidf_(h0), t1 = h1 * sigmoidf_(h1);
            float t2 = h2 * sigmoidf_(h2), t3 = h3 * sigmoidf_(h3);
            *(uint32_t*)(smraw + OB_T + r0 * 272 + n * 2)       = pack_h2(t0, t1);
            *(uint32_t*)(smraw + OB_T + (r0 + 8) * 272 + n * 2) = pack_h2(t2, t3);
        }
    }
    __syncthreads();

    // stage Wgp hi/lo, Wv (norm region dead)
    for (int q = tid; q < 1024; q += 256) {
        ((uint32_t*)(smraw + OB_WGP))[q]   = ((const uint32_t*)g_Wgphi)[q];
        ((uint32_t*)(smraw + OB_WGPLO))[q] = ((const uint32_t*)g_Wgplo)[q];
    }
    for (int q = tid; q < 528; q += 256) smf[OB_WV / 4 + q] = Wv[q];

    // ================= GEMM2: m_s = T @ W2 (K=128) + fused gate ==============
    float gacc[2][2][4];
#pragma unroll
    for (int mt = 0; mt < 2; ++mt) {
#pragma unroll
        for (int nt = 0; nt < 8; ++nt)
#pragma unroll
            for (int r = 0; r < 4; ++r) acc[mt][nt][r] = 0.0f;
#pragma unroll
        for (int gn = 0; gn < 2; ++gn)
#pragma unroll
            for (int r = 0; r < 4; ++r) gacc[mt][gn][r] = 0.0f;
    }

    wh = *(const uint4*)&g_W2hi[wkk * 128 + wn8];
    wl = *(const uint4*)&g_W2lo[wkk * 128 + wn8];
    *(uint4*)(smraw + WBUF(0) + wkk * 272 + wn8 * 2) = wh;
    *(uint4*)(smraw + WBUF(0) + WLO_OFF + wkk * 272 + wn8 * 2) = wl;
    __syncthreads();

    for (int kt = 0; kt < 8; ++kt) {
        const int cur = kt & 1, nxt = cur ^ 1;
        const bool more = (kt + 1 < 8);
        if (more) {
            wh = *(const uint4*)&g_W2hi[((kt + 1) * 16 + wkk) * 128 + wn8];
            wl = *(const uint4*)&g_W2lo[((kt + 1) * 16 + wkk) * 128 + wn8];
        }
        {
            uint32_t ah[2][4];
#pragma unroll
            for (int mt = 0; mt < 2; ++mt)
                ldsm4(smb + OB_T + (mw + 16 * mt + arow) * 272 + (kt * 16 + acol * 8) * 2,
                      ah[mt]);
#pragma unroll
            for (int nb = 0; nb < 4; ++nb) {
                uint32_t bh[4], bl[4];
                uint32_t baddr = smb + WBUF(cur) + arow * 272 + (nw + nb * 16 + acol * 8) * 2;
                ldsm4t(baddr, bh);
                ldsm4t(baddr + WLO_OFF, bl);
#pragma unroll
                for (int mt = 0; mt < 2; ++mt) {
                    mma_f16(acc[mt][2 * nb],     ah[mt], bh);
                    mma_f16(acc[mt][2 * nb + 1], ah[mt], bh + 2);
                    mma_f16(acc[mt][2 * nb],     ah[mt], bl);
                    mma_f16(acc[mt][2 * nb + 1], ah[mt], bl + 2);
                }
            }
            // fused gate: 16 extra N columns (Wgp tile = 512B contiguous per kt)
            {
                uint32_t gh[4], gl[4];
                uint32_t gaddr = smb + OB_WGP + kt * 512 + arow * 32 + acol * 16;
                ldsm4t(gaddr, gh);
                ldsm4t(gaddr + (OB_WGPLO - OB_WGP), gl);
#pragma unroll
                for (int mt = 0; mt < 2; ++mt) {
                    mma_f16(gacc[mt][0], ah[mt], gh);
                    mma_f16(gacc[mt][1], ah[mt], gh + 2);
                    mma_f16(gacc[mt][0], ah[mt], gl);
                    mma_f16(gacc[mt][1], ah[mt], gl + 2);
                }
            }
        }
        if (more) {
            *(uint4*)(smraw + WBUF(nxt) + wkk * 272 + wn8 * 2) = wh;
            *(uint4*)(smraw + WBUF(nxt) + WLO_OFF + wkk * 272 + wn8 * 2) = wl;
        }
        __syncthreads();
    }

    // ---- epilogue 2: +b2 -> sms ; gate sigmoid -> sg ----
    float* sms = smf;        // [128][132] (aliases T; reads complete)
    float* sg = smf + OB_SG / 4;  // [128][16]
#pragma unroll
    for (int mt = 0; mt < 2; ++mt) {
        int r0 = mw + 16 * mt + (lane >> 2);
#pragma unroll
        for (int nt = 0; nt < 8; ++nt) {
            int n = nw + nt * 8 + (lane & 3) * 2;
            float2 bb = *(const float2*)&b2[n];
            sms[r0 * 132 + n]       = acc[mt][nt][0] + bb.x;
            sms[r0 * 132 + n + 1]   = acc[mt][nt][1] + bb.y;
            sms[(r0 + 8) * 132 + n]     = acc[mt][nt][2] + bb.x;
            sms[(r0 + 8) * 132 + n + 1] = acc[mt][nt][3] + bb.y;
        }
#pragma unroll
        for (int gn = 0; gn < 2; ++gn) {
            int col = gn * 8 + (lane & 3) * 2;
            float b0 = g_bgp[col], b1g = g_bgp[col + 1];
            sg[r0 * 16 + col]           = sigmoidf_(gacc[mt][gn][0] + b0);
            sg[r0 * 16 + col + 1]       = sigmoidf_(gacc[mt][gn][1] + b1g);
            sg[(r0 + 8) * 16 + col]     = sigmoidf_(gacc[mt][gn][2] + b0);
            sg[(r0 + 8) * 16 + col + 1] = sigmoidf_(gacc[mt][gn][3] + b1g);
        }
    }
    __syncthreads();

    // ---- scatter-add m_s ----
    for (int q = tid; q < 4096; q += 256) {
        int e = q >> 5, cq = q & 31;
        if (e < nval) {
            const float* p = sms + e * 132 + cq * 4;
            red4(&g_agg_s[(size_t)sdst[e] * 128 + cq * 4], p[0], p[1], p[2], p[3]);
        }
    }
    __syncthreads();

    // ---- gather vin (aliases sms, dead) ----
    float* svin = smf;  // [128][100]
    for (int q = tid; q < 128 * 99; q += 256) {
        int e = q / 99, j = q - e * 99;
        int eg = e0 + min(e, nval - 1);
        float val;
        if (j < 48)      val = v[(size_t)ssrc[e] * 48 + j];
        else if (j < 96) val = v[(size_t)sdst[e] * 48 + (j - 48)];
        else             val = ev[(size_t)eg * 3 + (j - 96)];
        svin[e * 100 + j] = val;
    }
    __syncthreads();

    // ---- v projection * gate, scatter-add ----
    for (int q = tid; q < 1536; q += 256) {
        int e = q / 12, rq = q - e * 12;
        if (e >= nval) continue;
        float out[4];
#pragma unroll
        for (int u = 0; u < 4; ++u) {
            int r = rq * 4 + u, w = r / 3, c3 = r - w * 3;
            float a = 0.0f;
#pragma unroll
            for (int j = 0; j < 33; ++j)
                a = fmaf(svin[e * 100 + j * 3 + c3], smf[OB_WV / 4 + j * 16 + w], a);
            out[u] = a * sg[e * 16 + w];
        }
        red4(&g_agg_v[(size_t)sdst[e] * 48 + rq * 4], out[0], out[1], out[2], out[3]);
    }
}

// ---------------------------------------------------------------------------
// Node update kernel (r1, verified correct)
// ---------------------------------------------------------------------------
__global__ __launch_bounds__(128) void node_kernel(
    const float* __restrict__ s, const float* __restrict__ v,
    const float* __restrict__ W1, const float* __restrict__ b1,
    const float* __restrict__ W2, const float* __restrict__ b2,
    const float* __restrict__ Wv, const float* __restrict__ Wg,
    const float* __restrict__ bg, const float* __restrict__ lng,
    const float* __restrict__ lnb,
    float* __restrict__ out_s, float* __restrict__ out_v, int n)
{
    __shared__ float xu[8][292];
    __shared__ float vin[8][96];
    __shared__ float tt[8][128];
    __shared__ float dsm[8][132];
    __shared__ float gate[8][16];
    __shared__ float rsum[8][4], rsq[8][4];

    const int tid = threadIdx.x;
    const int n0 = blockIdx.x * 8;

    for (int idx = tid; idx < 8 * 256; idx += 128) {
        int i = idx >> 8, k = idx & 255;
        int nd = min(n0 + i, n - 1);
        xu[i][k] = (k < 128) ? s[nd * 128 + k] : g_agg_s[nd * 128 + (k - 128)];
    }
    for (int idx = tid; idx < 8 * 96; idx += 128) {
        int i = idx / 96, k = idx - i * 96;
        int nd = min(n0 + i, n - 1);
        vin[i][k] = (k < 48) ? v[nd * 48 + k] : g_agg_v[nd * 48 + (k - 48)];
    }
    __syncthreads();
    for (int idx = tid; idx < 8 * 32; idx += 128) {
        int i = idx >> 5, j = idx & 31;
        float a = vin[i][j * 3], b = vin[i][j * 3 + 1], c = vin[i][j * 3 + 2];
        xu[i][256 + j] = sqrtf(fmaxf(a * a + b * b + c * c, 1e-8f));
    }
    __syncthreads();

    const int c = tid;
    float acc[8];
    {
        float bb = b1[c];
#pragma unroll
        for (int i = 0; i < 8; ++i) acc[i] = bb;
    }
    for (int k = 0; k < 288; ++k) {
        float w = W1[k * 128 + c];
#pragma unroll
        for (int i = 0; i < 8; ++i) acc[i] = fmaf(xu[i][k], w, acc[i]);
    }
#pragma unroll
    for (int i = 0; i < 8; ++i) {
        float h = acc[i];
        tt[i][c] = h * sigmoidf_(h);
    }
    __syncthreads();

    float acc2[8];
    {
        float bb = b2[c];
#pragma unroll
        for (int i = 0; i < 8; ++i) acc2[i] = bb;
    }
    for (int k = 0; k < 128; ++k) {
        float w = W2[k * 128 + c];
#pragma unroll
        for (int i = 0; i < 8; ++i) acc2[i] = fmaf(tt[i][k], w, acc2[i]);
    }
#pragma unroll
    for (int i = 0; i < 8; ++i) dsm[i][c] = acc2[i];
    __syncthreads();

    {
        int i = tid >> 4, w = tid & 15;
        float g = bg[w];
        for (int cc = 0; cc < 128; ++cc)
            g = fmaf(dsm[i][cc], Wg[cc * 16 + w], g);
        gate[i][w] = sigmoidf_(g);
    }

    float val[8];
#pragma unroll
    for (int i = 0; i < 8; ++i) {
        int nd = min(n0 + i, n - 1);
        val[i] = s[nd * 128 + c] + acc2[i];
    }
    const int lane = tid & 31, wq = tid >> 5;
    float psum[8], psq[8];
#pragma unroll
    for (int i = 0; i < 8; ++i) { psum[i] = val[i]; psq[i] = val[i] * val[i]; }
#pragma unroll
    for (int off = 16; off > 0; off >>= 1) {
#pragma unroll
        for (int i = 0; i < 8; ++i) {
            psum[i] += __shfl_xor_sync(0xffffffffu, psum[i], off);
            psq[i]  += __shfl_xor_sync(0xffffffffu, psq[i],  off);
        }
    }
    if (lane == 0) {
#pragma unroll
        for (int i = 0; i < 8; ++i) { rsum[i][wq] = psum[i]; rsq[i][wq] = psq[i]; }
    }
    __syncthreads();

#pragma unroll
    for (int i = 0; i < 8; ++i) {
        if (n0 + i >= n) continue;
        float sum = rsum[i][0] + rsum[i][1] + rsum[i][2] + rsum[i][3];
        float sq  = rsq[i][0] + rsq[i][1] + rsq[i][2] + rsq[i][3];
        float mu  = sum * (1.0f / 128.0f);
        float var = sq * (1.0f / 128.0f) - mu * mu;
        float o = (val[i] - mu) * rsqrtf(var + 1e-5f) * lng[c] + lnb[c];
        out_s[(n0 + i) * 128 + c] = o;
    }

    for (int q = tid; q < 8 * 48; q += 128) {
        int i = q / 48, r = q - i * 48;
        if (n0 + i >= n) continue;
        int w = r / 3, cc = r - w * 3;
        float a = 0.0f;
#pragma unroll
        for (int j = 0; j < 32; ++j)
            a = fmaf(vin[i][j * 3 + cc], Wv[j * 16 + w], a);
        a *= gate[i][w];
        out_v[(n0 + i) * 48 + r] = v[(n0 + i) * 48 + r] + a;
    }
}

// ---------------------------------------------------------------------------
extern "C" void kernel_launch(void* const* d_in, const int* in_sizes, int n_in,
                              void* d_out, int out_size)
{
    const float* s   = (const float*)d_in[0];
    const float* v   = (const float*)d_in[1];
    const int*   ei  = (const int*)  d_in[2];
    const float* es  = (const float*)d_in[3];
    const float* ev  = (const float*)d_in[4];
    const float* mW1 = (const float*)d_in[5];
    const float* mb1 = (const float*)d_in[6];
    const float* mW2 = (const float*)d_in[7];
    const float* mb2 = (const float*)d_in[8];
    const float* mWv = (const float*)d_in[9];
    const float* mWg = (const float*)d_in[10];
    const float* mbg = (const float*)d_in[11];
    const float* uW1 = (const float*)d_in[12];
    const float* ub1 = (const float*)d_in[13];
    const float* uW2 = (const float*)d_in[14];
    const float* ub2 = (const float*)d_in[15];
    const float* uWv = (const float*)d_in[16];
    const float* uWg = (const float*)d_in[17];
    const float* ubg = (const float*)d_in[18];
    const float* lng = (const float*)d_in[19];
    const float* lnb = (const float*)d_in[20];

    const int n = in_sizes[0] / 128;
    const int E = in_sizes[2] / 2;

    float* out_s = (float*)d_out;
    float* out_v = out_s + (size_t)n * 128;

    cudaFuncSetAttribute(edge_kernel,
                         cudaFuncAttributeMaxDynamicSharedMemorySize,
                         EDGE_SMEM_BYTES);

    zero_kernel<<<(n * 176 + 255) / 256, 256>>>(n);
    prep_weights<<<(61456 + 255) / 256, 256>>>(mW1, mW2, mb2, mWg, mbg);
    y_kernel<<<(n + 127) / 128, 256>>>(s, n);

    edge_kernel<<<(E + 127) / 128, 256, EDGE_SMEM_BYTES>>>(
        s, v, ei, es, ev, mb1, mb2, mWv, E);

    node_kernel<<<(n + 7) / 8, 128>>>(
        s, v, uW1, ub1, uW2, ub2, uWv, uWg, ubg, lng, lnb,
        out_s, out_v, n);
}

// round 12
// speedup vs baseline: 3.4189x; 1.6330x over previous
#include <cuda_runtime.h>
#include <cuda_fp16.h>
#include <math.h>
#include <stdint.h>

// Problem constants: N=20000, E=640000, S=128, V=16, E_DIM=32
#define MAXN 20000

__device__ float g_agg_s[MAXN * 128];
__device__ float g_agg_v[MAXN * 48];

// Per-node precomputed: Y1 = s @ W1[0:128], Y2 = s @ W1[128:256]
__device__ float g_Y1[MAXN * 128];
__device__ float g_Y2[MAXN * 128];
// Per-node vector norms and v-projection partials
__device__ float g_vn[MAXN * 16];
__device__ float g_VA[MAXN * 48];   // v @ Wv[0:16]   (src role)
__device__ float g_VB[MAXN * 48];   // v @ Wv[16:32]  (dst role)

// Pre-converted fp16 hi/lo weights (row-major [k][n]).
__device__ __half g_W1ahi[128 * 128];  // W1 rows 0..127
__device__ __half g_W1alo[128 * 128];
__device__ __half g_W1bhi[128 * 128];  // W1 rows 128..255
__device__ __half g_W1blo[128 * 128];
__device__ __half g_W1phi[80 * 128];   // W1 rows 256..321 (edge-local), padded to 80
__device__ __half g_W1plo[80 * 128];
__device__ __half g_W2hi[128 * 128];
__device__ __half g_W2lo[128 * 128];
__device__ __half g_Wgphi[128 * 16];   // W2 @ Wg (fused gate)
__device__ __half g_Wgplo[128 * 16];
__device__ float  g_bgp[16];           // b2 @ Wg + bg

__device__ __forceinline__ float sigmoidf_(float x) {
    return 1.0f / (1.0f + __expf(-x));
}
__device__ __forceinline__ uint32_t smem_to_u32(const void* p) {
    uint32_t a;
    asm("{ .reg .u64 t; cvta.to.shared.u64 t, %1; cvt.u32.u64 %0, t; }"
        : "=r"(a) : "l"(p));
    return a;
}
__device__ __forceinline__ void ldsm4(uint32_t addr, uint32_t* r) {
    asm volatile("ldmatrix.sync.aligned.m8n8.x4.shared.b16 {%0,%1,%2,%3}, [%4];"
        : "=r"(r[0]), "=r"(r[1]), "=r"(r[2]), "=r"(r[3]) : "r"(addr));
}
__device__ __forceinline__ void ldsm4t(uint32_t addr, uint32_t* r) {
    asm volatile("ldmatrix.sync.aligned.m8n8.x4.trans.shared.b16 {%0,%1,%2,%3}, [%4];"
        : "=r"(r[0]), "=r"(r[1]), "=r"(r[2]), "=r"(r[3]) : "r"(addr));
}
__device__ __forceinline__ void mma_f16(float* c, const uint32_t* a, const uint32_t* b) {
    asm volatile(
        "mma.sync.aligned.m16n8k16.row.col.f32.f16.f16.f32 "
        "{%0,%1,%2,%3}, {%4,%5,%6,%7}, {%8,%9}, {%0,%1,%2,%3};"
        : "+f"(c[0]), "+f"(c[1]), "+f"(c[2]), "+f"(c[3])
        : "r"(a[0]), "r"(a[1]), "r"(a[2]), "r"(a[3]), "r"(b[0]), "r"(b[1]));
}
__device__ __forceinline__ uint32_t pack_h2(float x0, float x1) {
    __half2 t = __floats2half2_rn(x0, x1);
    return *(uint32_t*)&t;
}
__device__ __forceinline__ void red4(float* p, float a, float b, float c, float d) {
    asm volatile("red.global.add.v4.f32 [%0], {%1, %2, %3, %4};"
        :: "l"(p), "f"(a), "f"(b), "f"(c), "f"(d) : "memory");
}

// ---------------------------------------------------------------------------
__global__ void zero_kernel(int n) {
    int total = n * 176;
    for (int i = blockIdx.x * blockDim.x + threadIdx.x; i < total;
         i += gridDim.x * blockDim.x) {
        if (i < n * 128) g_agg_s[i] = 0.0f;
        else             g_agg_v[i - n * 128] = 0.0f;
    }
}

// One-time weight conversion / fusion.
__global__ void prep_weights(const float* __restrict__ W1,
                             const float* __restrict__ W2,
                             const float* __restrict__ b2,
                             const float* __restrict__ Wg,
                             const float* __restrict__ bg) {
    int i = blockIdx.x * blockDim.x + threadIdx.x;
    if (i < 80 * 128) {
        int k = i >> 7;
        float val = (k < 66) ? W1[(256 + k) * 128 + (i & 127)] : 0.0f;
        __half h = __float2half_rn(val);
        g_W1phi[i] = h;
        g_W1plo[i] = __float2half_rn(val - __half2float(h));
    } else if (i < 26624) {
        int j = i - 10240;
        float val = W1[j];
        __half h = __float2half_rn(val);
        g_W1ahi[j] = h;
        g_W1alo[j] = __float2half_rn(val - __half2float(h));
    } else if (i < 43008) {
        int j = i - 26624;
        float val = W1[128 * 128 + j];
        __half h = __float2half_rn(val);
        g_W1bhi[j] = h;
        g_W1blo[j] = __float2half_rn(val - __half2float(h));
    } else if (i < 59392) {
        int j = i - 43008;
        float val = W2[j];
        __half h = __float2half_rn(val);
        g_W2hi[j] = h;
        g_W2lo[j] = __float2half_rn(val - __half2float(h));
    } else if (i < 61440) {
        int j = i - 59392;
        int k = j >> 4, w = j & 15;
        float a = 0.0f;
        for (int c = 0; c < 128; ++c)
            a = fmaf(W2[k * 128 + c], Wg[c * 16 + w], a);
        __half h = __float2half_rn(a);
        g_Wgphi[j] = h;
        g_Wgplo[j] = __float2half_rn(a - __half2float(h));
    } else if (i < 61456) {
        int w = i - 61440;
        float a = bg[w];
        for (int c = 0; c < 128; ++c)
            a = fmaf(b2[c], Wg[c * 16 + w], a);
        g_bgp[w] = a;
    }
}

// ---------------------------------------------------------------------------
// Per-node prep: vector norms + v-projection partials (VA = v@Wv[0:16],
// VB = v@Wv[16:32]). 32 nodes/CTA.
// ---------------------------------------------------------------------------
__global__ __launch_bounds__(256) void prep_nodes(const float* __restrict__ v,
                                                  const float* __restrict__ Wv,
                                                  int n) {
    __shared__ float sv[32 * 48];
    __shared__ float sw[528];
    const int tid = threadIdx.x;
    const int n0 = blockIdx.x * 32;

    for (int q = tid; q < 32 * 48; q += 256) {
        int i = q / 48, k = q - i * 48;
        int nd = min(n0 + i, n - 1);
        sv[q] = v[(size_t)nd * 48 + k];
    }
    for (int q = tid; q < 528; q += 256) sw[q] = Wv[q];
    __syncthreads();

    for (int q = tid; q < 32 * 16; q += 256) {
        int i = q >> 4, j = q & 15;
        if (n0 + i >= n) continue;
        float a = sv[i * 48 + j * 3], b = sv[i * 48 + j * 3 + 1],
              c = sv[i * 48 + j * 3 + 2];
        g_vn[(size_t)(n0 + i) * 16 + j] = sqrtf(fmaxf(a * a + b * b + c * c, 1e-8f));
    }
    for (int q = tid; q < 32 * 48; q += 256) {
        int i = q / 48, r = q - i * 48;
        if (n0 + i >= n) continue;
        int w = r / 3, c = r - w * 3;
        float a = 0.0f, b = 0.0f;
#pragma unroll
        for (int j = 0; j < 16; ++j) {
            float vv = sv[i * 48 + j * 3 + c];
            a = fmaf(vv, sw[j * 16 + w], a);
            b = fmaf(vv, sw[(16 + j) * 16 + w], b);
        }
        g_VA[(size_t)(n0 + i) * 48 + r] = a;
        g_VB[(size_t)(n0 + i) * 48 + r] = b;
    }
}

// ---------------------------------------------------------------------------
// Y kernel: per-node partials Y1 = s @ W1a, Y2 = s @ W1b (fp16 2-term, mma).
// ---------------------------------------------------------------------------
__global__ __launch_bounds__(256) void y_kernel(const float* __restrict__ s, int n) {
    __shared__ __align__(16) char ysm[6144 + 8704];
    const uint32_t smb = smem_to_u32(ysm);
    const int tid = threadIdx.x;
    const int lane = tid & 31;
    const int wid = tid >> 5;
    const int n0 = blockIdx.x * 128;

    const int mw = (wid & 3) * 32;
    const int nw = (wid >> 2) * 64;
    const int arow = lane & 15;
    const int acol = lane >> 4;

    for (int g = 0; g < 2; ++g) {
        const __half* Whi = g ? g_W1bhi : g_W1ahi;
        const __half* Wlo = g ? g_W1blo : g_W1alo;
        float acc[2][8][4];
#pragma unroll
        for (int mt = 0; mt < 2; ++mt)
#pragma unroll
            for (int nt = 0; nt < 8; ++nt)
#pragma unroll
                for (int r = 0; r < 4; ++r) acc[mt][nt][r] = 0.0f;

        for (int kt = 0; kt < 8; ++kt) {
            for (int q = tid; q < 2048; q += 256) {
                int e = q >> 4, kk = q & 15;
                int nd = min(n0 + e, n - 1);
                *(__half*)(ysm + e * 48 + kk * 2) =
                    __float2half_rn(s[nd * 128 + kt * 16 + kk]);
            }
            for (int q = tid; q < 2048; q += 256) {
                int kk = q >> 7, nc = q & 127;
                *(__half*)(ysm + 6144 + kk * 272 + nc * 2) = Whi[(kt * 16 + kk) * 128 + nc];
                *(__half*)(ysm + 6144 + 4352 + kk * 272 + nc * 2) = Wlo[(kt * 16 + kk) * 128 + nc];
            }
            __syncthreads();
            uint32_t ah[2][4];
#pragma unroll
            for (int mt = 0; mt < 2; ++mt)
                ldsm4(smb + (mw + 16 * mt + arow) * 48 + acol * 16, ah[mt]);
#pragma unroll
            for (int nb = 0; nb < 4; ++nb) {
                uint32_t bh[4], bl[4];
                uint32_t baddr = smb + 6144 + arow * 272 + (nw + nb * 16 + acol * 8) * 2;
                ldsm4t(baddr, bh);
                ldsm4t(baddr + 4352, bl);
#pragma unroll
                for (int mt = 0; mt < 2; ++mt) {
                    mma_f16(acc[mt][2 * nb],     ah[mt], bh);
                    mma_f16(acc[mt][2 * nb + 1], ah[mt], bh + 2);
                    mma_f16(acc[mt][2 * nb],     ah[mt], bl);
                    mma_f16(acc[mt][2 * nb + 1], ah[mt], bl + 2);
                }
            }
            __syncthreads();
        }
        float* Y = g ? g_Y2 : g_Y1;
#pragma unroll
        for (int mt = 0; mt < 2; ++mt) {
            int r0 = mw + 16 * mt + (lane >> 2);
#pragma unroll
            for (int nt = 0; nt < 8; ++nt) {
                int nc = nw + nt * 8 + (lane & 3) * 2;
                if (n0 + r0 < n) {
                    float2 u = make_float2(acc[mt][nt][0], acc[mt][nt][1]);
                    *(float2*)&Y[(size_t)(n0 + r0) * 128 + nc] = u;
                }
                if (n0 + r0 + 8 < n) {
                    float2 u = make_float2(acc[mt][nt][2], acc[mt][nt][3]);
                    *(float2*)&Y[(size_t)(n0 + r0 + 8) * 128 + nc] = u;
                }
            }
        }
    }
}

// ===========================================================================
// Edge kernel: 128 edges/CTA, 256 threads.
// GEMM1 K=80 only (node parts in Y1/Y2 acc init); gate fused into GEMM2.
// v-norms and v-projection partials precomputed per node (g_vn, g_VA, g_VB).
// smem byte map (total 106624):
//   [0,34816)      T [128][136]fp16 (GEMM2 A); later sms f32[128][132] (0..67584)
//   [34816,47104)  X tile dbl-buf (GEMM1)
//   [67584,69632)  sev f32[128][4] (ev + |ev|)  — dead zone between sms end & snorm
//   [69632,88064)  snorm f32[128][36] (GEMM1 only); after epi1: Wgp hi/lo @69632
//   [79936,88128)  sg f32[128][16] (written epi2, snorm dead)
//   [88128,88192)  wv32 f32[16]
//   [88192,105600) W tile dbl-buf
//   [105600,106624) ssrc / sdst
// Lifetime check: sev written ph1, read at end; sms spans [0,67584) exactly;
// sg/Wgp only written after GEMM1 (snorm dead); wv32 in the 64B gap before W bufs.
// ===========================================================================
#define OB_T     0
#define OB_X     34816
#define OB_SEV   67584
#define OB_NORM  69632
#define OB_WGP   69632
#define OB_WGPLO 73728
#define OB_SG    79936
#define OB_WV32  88128
#define OB_W     88192
#define OB_SRC   105600
#define OB_DST   106112
#define EDGE_SMEM_BYTES 106624
#define XBUF(b)  (OB_X + (b) * 6144)
#define WBUF(b)  (OB_W + (b) * 8704)
#define WLO_OFF  4352

// edge-local X: k 0..31 edge_s, 32 edge_len, 33..65 vn (src16,dst16,|ev|), 66..79 zero
__device__ __forceinline__ float fetch_x80(int k, int e, int eg,
    const float* __restrict__ es, const float* snorm)
{
    if (k < 32)   return es[eg * 32 + k];
    if (k == 32)  return snorm[e * 36 + 32];
    if (k < 66)   return snorm[e * 36 + (k - 33)];
    return 0.0f;
}

__global__ __launch_bounds__(256, 2) void edge_kernel(
    const int* __restrict__ ei, const float* __restrict__ es,
    const float* __restrict__ ev,
    const float* __restrict__ b1, const float* __restrict__ b2,
    const float* __restrict__ Wv, int E)
{
    extern __shared__ __align__(16) char smraw[];
    float* smf = (float*)smraw;
    const uint32_t smb = smem_to_u32(smraw);

    const int tid = threadIdx.x;
    const int lane = tid & 31;
    const int wid = tid >> 5;
    const int e0 = blockIdx.x * 128;
    const int nval = min(128, E - e0);

    int* ssrc = (int*)(smraw + OB_SRC);
    int* sdst = (int*)(smraw + OB_DST);
    float* snorm = (float*)(smraw + OB_NORM);

    // ---- phase 1: indices, vn staging, ev ----
    if (tid < 128) {
        int ee = e0 + min(tid, nval - 1);
        ssrc[tid] = ei[ee];
        sdst[tid] = ei[E + ee];
    }
    if (tid >= 240) {  // 16 threads stage Wv row 32 (to 64B gap @88128)
        smf[OB_WV32 / 4 + (tid - 240)] = Wv[32 * 16 + (tid - 240)];
    }
    __syncthreads();
    for (int q = tid; q < 1024; q += 256) {
        int e = q >> 3, p = q & 7;
        float4 t = (p < 4)
            ? *(const float4*)&g_vn[(size_t)ssrc[e] * 16 + p * 4]
            : *(const float4*)&g_vn[(size_t)sdst[e] * 16 + (p - 4) * 4];
        *(float4*)&snorm[e * 36 + (p < 4 ? p * 4 : 16 + (p - 4) * 4)] = t;
    }
    if (tid < 128) {
        int eg = e0 + min(tid, nval - 1);
        float a = ev[eg * 3], b = ev[eg * 3 + 1], c = ev[eg * 3 + 2];
        float nn = sqrtf(fmaxf(a * a + b * b + c * c, 1e-8f));
        snorm[tid * 36 + 32] = nn;
        float* se = smf + OB_SEV / 4 + tid * 4;
        se[0] = a; se[1] = b; se[2] = c; se[3] = nn;
    }
    __syncthreads();

    const int mw = (wid & 3) * 32;
    const int nw = (wid >> 2) * 64;
    const int arow = lane & 15;
    const int acol = lane >> 4;

    const int xe_base = tid >> 3;
    const int xk2 = (tid & 7) * 2;
    const int wkk = tid >> 4;
    const int wn8 = (tid & 15) * 8;

    float acc[2][8][4];

    // ---- acc init: Y1[src] + Y2[dst] fragments ----
    {
        const int rbase = mw + (lane >> 2);
        const int cbase = nw + (lane & 3) * 2;
#pragma unroll
        for (int mt = 0; mt < 2; ++mt) {
#pragma unroll
            for (int rh = 0; rh < 2; ++rh) {
                int r = rbase + 16 * mt + 8 * rh;
                const float* y1 = g_Y1 + (size_t)ssrc[r] * 128;
                const float* y2 = g_Y2 + (size_t)sdst[r] * 128;
#pragma unroll
                for (int nt = 0; nt < 8; ++nt) {
                    int nc = cbase + nt * 8;
                    float2 a = *(const float2*)&y1[nc];
                    float2 b = *(const float2*)&y2[nc];
                    acc[mt][nt][2 * rh]     = a.x + b.x;
                    acc[mt][nt][2 * rh + 1] = a.y + b.y;
                }
            }
        }
    }

    float xr[4][2];
    uint4 wh, wl;

    // ---- prologue: tile 0 ----
    {
#pragma unroll
        for (int it = 0; it < 4; ++it) {
            int e = xe_base + it * 32;
            int eg = e0 + min(e, nval - 1);
            xr[it][0] = fetch_x80(xk2,     e, eg, es, snorm);
            xr[it][1] = fetch_x80(xk2 + 1, e, eg, es, snorm);
        }
        wh = *(const uint4*)&g_W1phi[wkk * 128 + wn8];
        wl = *(const uint4*)&g_W1plo[wkk * 128 + wn8];
#pragma unroll
        for (int it = 0; it < 4; ++it) {
            int e = xe_base + it * 32;
            *(uint32_t*)(smraw + XBUF(0) + e * 48 + xk2 * 2) =
                pack_h2(xr[it][0], xr[it][1]);
        }
        *(uint4*)(smraw + WBUF(0) + wkk * 272 + wn8 * 2) = wh;
        *(uint4*)(smraw + WBUF(0) + WLO_OFF + wkk * 272 + wn8 * 2) = wl;
    }
    __syncthreads();

    // ================= GEMM1: edge-local part, K=80 (5 tiles) ================
    for (int kt = 0; kt < 5; ++kt) {
        const int cur = kt & 1, nxt = cur ^ 1;
        const bool more = (kt + 1 < 5);
        if (more) {
            int kbase = (kt + 1) * 16;
#pragma unroll
            for (int it = 0; it < 4; ++it) {
                int e = xe_base + it * 32;
                int eg = e0 + min(e, nval - 1);
                xr[it][0] = fetch_x80(kbase + xk2,     e, eg, es, snorm);
                xr[it][1] = fetch_x80(kbase + xk2 + 1, e, eg, es, snorm);
            }
            wh = *(const uint4*)&g_W1phi[(kbase + wkk) * 128 + wn8];
            wl = *(const uint4*)&g_W1plo[(kbase + wkk) * 128 + wn8];
        }
        {
            uint32_t ah[2][4];
#pragma unroll
            for (int mt = 0; mt < 2; ++mt)
                ldsm4(smb + XBUF(cur) + (mw + 16 * mt + arow) * 48 + acol * 16, ah[mt]);
#pragma unroll
            for (int nb = 0; nb < 4; ++nb) {
                uint32_t bh[4], bl[4];
                uint32_t baddr = smb + WBUF(cur) + arow * 272 + (nw + nb * 16 + acol * 8) * 2;
                ldsm4t(baddr, bh);
                ldsm4t(baddr + WLO_OFF, bl);
#pragma unroll
                for (int mt = 0; mt < 2; ++mt) {
                    mma_f16(acc[mt][2 * nb],     ah[mt], bh);
                    mma_f16(acc[mt][2 * nb + 1], ah[mt], bh + 2);
                    mma_f16(acc[mt][2 * nb],     ah[mt], bl);
                    mma_f16(acc[mt][2 * nb + 1], ah[mt], bl + 2);
                }
            }
        }
        if (more) {
#pragma unroll
            for (int it = 0; it < 4; ++it) {
                int e = xe_base + it * 32;
                *(uint32_t*)(smraw + XBUF(nxt) + e * 48 + xk2 * 2) =
                    pack_h2(xr[it][0], xr[it][1]);
            }
            *(uint4*)(smraw + WBUF(nxt) + wkk * 272 + wn8 * 2) = wh;
            *(uint4*)(smraw + WBUF(nxt) + WLO_OFF + wkk * 272 + wn8 * 2) = wl;
        }
        __syncthreads();
    }

    // ---- epilogue 1: +b1, silu -> T fp16 ----
#pragma unroll
    for (int mt = 0; mt < 2; ++mt) {
        int r0 = mw + 16 * mt + (lane >> 2);
#pragma unroll
        for (int nt = 0; nt < 8; ++nt) {
            int n = nw + nt * 8 + (lane & 3) * 2;
            float2 bb = *(const float2*)&b1[n];
            float h0 = acc[mt][nt][0] + bb.x, h1 = acc[mt][nt][1] + bb.y;
            float h2 = acc[mt][nt][2] + bb.x, h3 = acc[mt][nt][3] + bb.y;
            float t0 = h0 * sigmoidf_(h0), t1 = h1 * sigmoidf_(h1);
            float t2 = h2 * sigmoidf_(h2), t3 = h3 * sigmoidf_(h3);
            *(uint32_t*)(smraw + OB_T + r0 * 272 + n * 2)       = pack_h2(t0, t1);
            *(uint32_t*)(smraw + OB_T + (r0 + 8) * 272 + n * 2) = pack_h2(t2, t3);
        }
    }
    __syncthreads();

    // stage Wgp hi/lo (norm region dead after GEMM1)
    for (int q = tid; q < 1024; q += 256) {
        ((uint32_t*)(smraw + OB_WGP))[q]   = ((const uint32_t*)g_Wgphi)[q];
        ((uint32_t*)(smraw + OB_WGPLO))[q] = ((const uint32_t*)g_Wgplo)[q];
    }

    // ================= GEMM2: m_s = T @ W2 (K=128) + fused gate ==============
    float gacc[2][2][4];
#pragma unroll
    for (int mt = 0; mt < 2; ++mt) {
#pragma unroll
        for (int nt = 0; nt < 8; ++nt)
#pragma unroll
            for (int r = 0; r < 4; ++r) acc[mt][nt][r] = 0.0f;
#pragma unroll
        for (int gn = 0; gn < 2; ++gn)
#pragma unroll
            for (int r = 0; r < 4; ++r) gacc[mt][gn][r] = 0.0f;
    }

    wh = *(const uint4*)&g_W2hi[wkk * 128 + wn8];
    wl = *(const uint4*)&g_W2lo[wkk * 128 + wn8];
    *(uint4*)(smraw + WBUF(0) + wkk * 272 + wn8 * 2) = wh;
    *(uint4*)(smraw + WBUF(0) + WLO_OFF + wkk * 272 + wn8 * 2) = wl;
    __syncthreads();

    for (int kt = 0; kt < 8; ++kt) {
        const int cur = kt & 1, nxt = cur ^ 1;
        const bool more = (kt + 1 < 8);
        if (more) {
            wh = *(const uint4*)&g_W2hi[((kt + 1) * 16 + wkk) * 128 + wn8];
            wl = *(const uint4*)&g_W2lo[((kt + 1) * 16 + wkk) * 128 + wn8];
        }
        {
            uint32_t ah[2][4];
#pragma unroll
            for (int mt = 0; mt < 2; ++mt)
                ldsm4(smb + OB_T + (mw + 16 * mt + arow) * 272 + (kt * 16 + acol * 8) * 2,
                      ah[mt]);
#pragma unroll
            for (int nb = 0; nb < 4; ++nb) {
                uint32_t bh[4], bl[4];
                uint32_t baddr = smb + WBUF(cur) + arow * 272 + (nw + nb * 16 + acol * 8) * 2;
                ldsm4t(baddr, bh);
                ldsm4t(baddr + WLO_OFF, bl);
#pragma unroll
                for (int mt = 0; mt < 2; ++mt) {
                    mma_f16(acc[mt][2 * nb],     ah[mt], bh);
                    mma_f16(acc[mt][2 * nb + 1], ah[mt], bh + 2);
                    mma_f16(acc[mt][2 * nb],     ah[mt], bl);
                    mma_f16(acc[mt][2 * nb + 1], ah[mt], bl + 2);
                }
            }
            // fused gate: 16 extra N columns
            {
                uint32_t gh[4], gl[4];
                uint32_t gaddr = smb + OB_WGP + kt * 512 + arow * 32 + acol * 16;
                ldsm4t(gaddr, gh);
                ldsm4t(gaddr + (OB_WGPLO - OB_WGP), gl);
#pragma unroll
                for (int mt = 0; mt < 2; ++mt) {
                    mma_f16(gacc[mt][0], ah[mt], gh);
                    mma_f16(gacc[mt][1], ah[mt], gh + 2);
                    mma_f16(gacc[mt][0], ah[mt], gl);
                    mma_f16(gacc[mt][1], ah[mt], gl + 2);
                }
            }
        }
        if (more) {
            *(uint4*)(smraw + WBUF(nxt) + wkk * 272 + wn8 * 2) = wh;
            *(uint4*)(smraw + WBUF(nxt) + WLO_OFF + wkk * 272 + wn8 * 2) = wl;
        }
        __syncthreads();
    }

    // ---- epilogue 2: +b2 -> sms ; gate sigmoid -> sg ----
    float* sms = smf;             // [128][132] (aliases T; reads complete)
    float* sg = smf + OB_SG / 4;  // [128][16]
#pragma unroll
    for (int mt = 0; mt < 2; ++mt) {
        int r0 = mw + 16 * mt + (lane >> 2);
#pragma unroll
        for (int nt = 0; nt < 8; ++nt) {
            int n = nw + nt * 8 + (lane & 3) * 2;
            float2 bb = *(const float2*)&b2[n];
            sms[r0 * 132 + n]       = acc[mt][nt][0] + bb.x;
            sms[r0 * 132 + n + 1]   = acc[mt][nt][1] + bb.y;
            sms[(r0 + 8) * 132 + n]     = acc[mt][nt][2] + bb.x;
            sms[(r0 + 8) * 132 + n + 1] = acc[mt][nt][3] + bb.y;
        }
#pragma unroll
        for (int gn = 0; gn < 2; ++gn) {
            int col = gn * 8 + (lane & 3) * 2;
            float b0 = g_bgp[col], b1g = g_bgp[col + 1];
            sg[r0 * 16 + col]           = sigmoidf_(gacc[mt][gn][0] + b0);
            sg[r0 * 16 + col + 1]       = sigmoidf_(gacc[mt][gn][1] + b1g);
            sg[(r0 + 8) * 16 + col]     = sigmoidf_(gacc[mt][gn][2] + b0);
            sg[(r0 + 8) * 16 + col + 1] = sigmoidf_(gacc[mt][gn][3] + b1g);
        }
    }
    __syncthreads();

    // ---- scatter-add m_s ----
    for (int q = tid; q < 4096; q += 256) {
        int e = q >> 5, cq = q & 31;
        if (e < nval) {
            const float* p = sms + e * 132 + cq * 4;
            red4(&g_agg_s[(size_t)sdst[e] * 128 + cq * 4], p[0], p[1], p[2], p[3]);
        }
    }

    // ---- v projection via precomputed VA/VB, scatter-add ----
    for (int q = tid; q < 1536; q += 256) {
        int e = q / 12, rq = q - e * 12;
        if (e >= nval) continue;
        float4 a4 = *(const float4*)&g_VA[(size_t)ssrc[e] * 48 + rq * 4];
        float4 b4 = *(const float4*)&g_VB[(size_t)sdst[e] * 48 + rq * 4];
        float av[4] = {a4.x + b4.x, a4.y + b4.y, a4.z + b4.z, a4.w + b4.w};
        float out[4];
#pragma unroll
        for (int u = 0; u < 4; ++u) {
            int r = rq * 4 + u, w = r / 3, c3 = r - w * 3;
            float val = av[u] + smf[OB_SEV / 4 + e * 4 + c3] * smf[OB_WV32 / 4 + w];
            out[u] = val * sg[e * 16 + w];
        }
        red4(&g_agg_v[(size_t)sdst[e] * 48 + rq * 4], out[0], out[1], out[2], out[3]);
    }
}

// ---------------------------------------------------------------------------
// Node update kernel (r1, verified correct)
// ---------------------------------------------------------------------------
__global__ __launch_bounds__(128) void node_kernel(
    const float* __restrict__ s, const float* __restrict__ v,
    const float* __restrict__ W1, const float* __restrict__ b1,
    const float* __restrict__ W2, const float* __restrict__ b2,
    const float* __restrict__ Wv, const float* __restrict__ Wg,
    const float* __restrict__ bg, const float* __restrict__ lng,
    const float* __restrict__ lnb,
    float* __restrict__ out_s, float* __restrict__ out_v, int n)
{
    __shared__ float xu[8][292];
    __shared__ float vin[8][96];
    __shared__ float tt[8][128];
    __shared__ float dsm[8][132];
    __shared__ float gate[8][16];
    __shared__ float rsum[8][4], rsq[8][4];

    const int tid = threadIdx.x;
    const int n0 = blockIdx.x * 8;

    for (int idx = tid; idx < 8 * 256; idx += 128) {
        int i = idx >> 8, k = idx & 255;
        int nd = min(n0 + i, n - 1);
        xu[i][k] = (k < 128) ? s[nd * 128 + k] : g_agg_s[nd * 128 + (k - 128)];
    }
    for (int idx = tid; idx < 8 * 96; idx += 128) {
        int i = idx / 96, k = idx - i * 96;
        int nd = min(n0 + i, n - 1);
        vin[i][k] = (k < 48) ? v[nd * 48 + k] : g_agg_v[nd * 48 + (k - 48)];
    }
    __syncthreads();
    for (int idx = tid; idx < 8 * 32; idx += 128) {
        int i = idx >> 5, j = idx & 31;
        float a = vin[i][j * 3], b = vin[i][j * 3 + 1], c = vin[i][j * 3 + 2];
        xu[i][256 + j] = sqrtf(fmaxf(a * a + b * b + c * c, 1e-8f));
    }
    __syncthreads();

    const int c = tid;
    float acc[8];
    {
        float bb = b1[c];
#pragma unroll
        for (int i = 0; i < 8; ++i) acc[i] = bb;
    }
    for (int k = 0; k < 288; ++k) {
        float w = W1[k * 128 + c];
#pragma unroll
        for (int i = 0; i < 8; ++i) acc[i] = fmaf(xu[i][k], w, acc[i]);
    }
#pragma unroll
    for (int i = 0; i < 8; ++i) {
        float h = acc[i];
        tt[i][c] = h * sigmoidf_(h);
    }
    __syncthreads();

    float acc2[8];
    {
        float bb = b2[c];
#pragma unroll
        for (int i = 0; i < 8; ++i) acc2[i] = bb;
    }
    for (int k = 0; k < 128; ++k) {
        float w = W2[k * 128 + c];
#pragma unroll
        for (int i = 0; i < 8; ++i) acc2[i] = fmaf(tt[i][k], w, acc2[i]);
    }
#pragma unroll
    for (int i = 0; i < 8; ++i) dsm[i][c] = acc2[i];
    __syncthreads();

    {
        int i = tid >> 4, w = tid & 15;
        float g = bg[w];
        for (int cc = 0; cc < 128; ++cc)
            g = fmaf(dsm[i][cc], Wg[cc * 16 + w], g);
        gate[i][w] = sigmoidf_(g);
    }

    float val[8];
#pragma unroll
    for (int i = 0; i < 8; ++i) {
        int nd = min(n0 + i, n - 1);
        val[i] = s[nd * 128 + c] + acc2[i];
    }
    const int lane = tid & 31, wq = tid >> 5;
    float psum[8], psq[8];
#pragma unroll
    for (int i = 0; i < 8; ++i) { psum[i] = val[i]; psq[i] = val[i] * val[i]; }
#pragma unroll
    for (int off = 16; off > 0; off >>= 1) {
#pragma unroll
        for (int i = 0; i < 8; ++i) {
            psum[i] += __shfl_xor_sync(0xffffffffu, psum[i], off);
            psq[i]  += __shfl_xor_sync(0xffffffffu, psq[i],  off);
        }
    }
    if (lane == 0) {
#pragma unroll
        for (int i = 0; i < 8; ++i) { rsum[i][wq] = psum[i]; rsq[i][wq] = psq[i]; }
    }
    __syncthreads();

#pragma unroll
    for (int i = 0; i < 8; ++i) {
        if (n0 + i >= n) continue;
        float sum = rsum[i][0] + rsum[i][1] + rsum[i][2] + rsum[i][3];
        float sq  = rsq[i][0] + rsq[i][1] + rsq[i][2] + rsq[i][3];
        float mu  = sum * (1.0f / 128.0f);
        float var = sq * (1.0f / 128.0f) - mu * mu;
        float o = (val[i] - mu) * rsqrtf(var + 1e-5f) * lng[c] + lnb[c];
        out_s[(n0 + i) * 128 + c] = o;
    }

    for (int q = tid; q < 8 * 48; q += 128) {
        int i = q / 48, r = q - i * 48;
        if (n0 + i >= n) continue;
        int w = r / 3, cc = r - w * 3;
        float a = 0.0f;
#pragma unroll
        for (int j = 0; j < 32; ++j)
            a = fmaf(vin[i][j * 3 + cc], Wv[j * 16 + w], a);
        a *= gate[i][w];
        out_v[(n0 + i) * 48 + r] = v[(n0 + i) * 48 + r] + a;
    }
}

// ---------------------------------------------------------------------------
extern "C" void kernel_launch(void* const* d_in, const int* in_sizes, int n_in,
                              void* d_out, int out_size)
{
    const float* s   = (const float*)d_in[0];
    const float* v   = (const float*)d_in[1];
    const int*   ei  = (const int*)  d_in[2];
    const float* es  = (const float*)d_in[3];
    const float* ev  = (const float*)d_in[4];
    const float* mW1 = (const float*)d_in[5];
    const float* mb1 = (const float*)d_in[6];
    const float* mW2 = (const float*)d_in[7];
    const float* mb2 = (const float*)d_in[8];
    const float* mWv = (const float*)d_in[9];
    const float* mWg = (const float*)d_in[10];
    const float* mbg = (const float*)d_in[11];
    const float* uW1 = (const float*)d_in[12];
    const float* ub1 = (const float*)d_in[13];
    const float* uW2 = (const float*)d_in[14];
    const float* ub2 = (const float*)d_in[15];
    const float* uWv = (const float*)d_in[16];
    const float* uWg = (const float*)d_in[17];
    const float* ubg = (const float*)d_in[18];
    const float* lng = (const float*)d_in[19];
    const float* lnb = (const float*)d_in[20];

    const int n = in_sizes[0] / 128;
    const int E = in_sizes[2] / 2;

    float* out_s = (float*)d_out;
    float* out_v = out_s + (size_t)n * 128;

    cudaFuncSetAttribute(edge_kernel,
                         cudaFuncAttributeMaxDynamicSharedMemorySize,
                         EDGE_SMEM_BYTES);

    zero_kernel<<<(n * 176 + 255) / 256, 256>>>(n);
    prep_weights<<<(61456 + 255) / 256, 256>>>(mW1, mW2, mb2, mWg, mbg);
    prep_nodes<<<(n + 31) / 32, 256>>>(v, mWv, n);
    y_kernel<<<(n + 127) / 128, 256>>>(s, n);

    edge_kernel<<<(E + 127) / 128, 256, EDGE_SMEM_BYTES>>>(
        ei, es, ev, mb1, mb2, mWv, E);

    node_kernel<<<(n + 7) / 8, 128>>>(
        s, v, uW1, ub1, uW2, ub2, uWv, uWg, ubg, lng, lnb,
        out_s, out_v, n);
}